// round 14
// baseline (speedup 1.0000x reference)
#include <cuda_runtime.h>
#include <cuda_fp16.h>
#include <cstdint>

#define D_IN   4096
#define N_FEAT 4096
#define BATCH  16384
#define TOPK   128
#define WCAND  1.2e-2f

// ---------------- device scratch (no allocs allowed) ------------------------
__device__ float  g_WT[(size_t)N_FEAT * D_IN];    // W^T fp32 [n][k] (exact fixup)
__device__ __half g_Wh[(size_t)D_IN * N_FEAT];    // W fp16  [k][n] (GEMM B)
__device__ __half g_Xh[(size_t)BATCH * D_IN];     // (x-pb) fp16 [m][k] (GEMM A)

// ---------------- helpers ---------------------------------------------------
__device__ __forceinline__ uint32_t smem_u32(const void* p) {
    uint32_t a;
    asm("{ .reg .u64 t; cvta.to.shared.u64 t, %1; cvt.u32.u64 %0, t; }"
        : "=r"(a) : "l"(p));
    return a;
}
__device__ __forceinline__ void mma_f16(float c[4], const uint32_t a[4],
                                        const uint32_t b[2]) {
    asm volatile(
        "mma.sync.aligned.m16n8k16.row.col.f32.f16.f16.f32 "
        "{%0,%1,%2,%3}, {%4,%5,%6,%7}, {%8,%9}, {%0,%1,%2,%3};"
        : "+f"(c[0]), "+f"(c[1]), "+f"(c[2]), "+f"(c[3])
        : "r"(a[0]), "r"(a[1]), "r"(a[2]), "r"(a[3]), "r"(b[0]), "r"(b[1]));
}
#define LDMATRIX_X4(r0, r1, r2, r3, addr) \
    asm volatile("ldmatrix.sync.aligned.m8n8.x4.shared.b16 {%0,%1,%2,%3}, [%4];" \
                 : "=r"(r0), "=r"(r1), "=r"(r2), "=r"(r3) : "r"(addr))
#define LDMATRIX_X4_T(r0, r1, r2, r3, addr) \
    asm volatile("ldmatrix.sync.aligned.m8n8.x4.trans.shared.b16 {%0,%1,%2,%3}, [%4];" \
                 : "=r"(r0), "=r"(r1), "=r"(r2), "=r"(r3) : "r"(addr))
#define CP_ASYNC16(dst_u32, src) \
    asm volatile("cp.async.cg.shared.global [%0], [%1], 16;" \
                 :: "r"(dst_u32), "l"(src) : "memory")
#define CP_COMMIT()  asm volatile("cp.async.commit_group;" ::: "memory")
#define CP_WAIT1()   asm volatile("cp.async.wait_group 1;" ::: "memory")

__device__ __forceinline__ uint32_t h2u(__half2 h) {
    return *reinterpret_cast<uint32_t*>(&h);
}

// ---------------- Prologue 0: x - pb -> fp16 g_Xh ---------------------------
__global__ __launch_bounds__(256) void convert_x(
    const float* __restrict__ x, const float* __restrict__ pb)
{
    const int i4 = blockIdx.x * 256 + threadIdx.x;
    const float4 v = reinterpret_cast<const float4*>(x)[i4];
    const float4 p = reinterpret_cast<const float4*>(pb)[i4 & (D_IN / 4 - 1)];
    uint2 o;
    o.x = h2u(__floats2half2_rn(v.x - p.x, v.y - p.y));
    o.y = h2u(__floats2half2_rn(v.z - p.z, v.w - p.w));
    reinterpret_cast<uint2*>(g_Xh)[i4] = o;
}

// ---------------- Prologue 1: W -> g_WT (fp32, transposed) + g_Wh (fp16) ----
__global__ void prep_w(const float* __restrict__ W) {
    __shared__ float t[32][33];
    const int n0 = blockIdx.x * 32, k0 = blockIdx.y * 32;
#pragma unroll
    for (int j = 0; j < 32; j += 8) {
        const int k = k0 + threadIdx.y + j;
        const float v = W[(size_t)k * N_FEAT + n0 + threadIdx.x];
        t[threadIdx.y + j][threadIdx.x] = v;
        g_Wh[(size_t)k * N_FEAT + n0 + threadIdx.x] = __float2half_rn(v);
    }
    __syncthreads();
#pragma unroll
    for (int j = 0; j < 32; j += 8)
        g_WT[(size_t)(n0 + threadIdx.y + j) * D_IN + k0 + threadIdx.x] =
            t[threadIdx.x][threadIdx.y + j];
}

// ---------------- Kernel 1: fp16 mma.sync GEMM + bias + relu ----------------
// Block 128(M) x 128(N) x 64(K): 64 iterations (half the syncs/waits of BK=32),
// 8 warps (4m x 2n), warp tile 32x64, 3-stage cp.async pipeline, 96KB smem ->
// still 2 CTAs/SM. A rows are full 128B SW128 atoms (chunk ^ (row&7)).
#define GM_BM 128
#define GM_BN 128
#define GM_BK 64
#define NIT   (D_IN / GM_BK)              // 64
#define STG   3
#define A_BYTES (GM_BM * GM_BK * 2)       // 16384
#define B_BYTES (GM_BK * GM_BN * 2)       // 16384
#define SM_BYTES (STG * (A_BYTES + B_BYTES))  // 98304

__global__ __launch_bounds__(256, 2) void encoder_gemm_h(
    const float* __restrict__ be, float* __restrict__ out)
{
    extern __shared__ char sm[];
    const uint32_t smb = smem_u32(sm);
    const uint32_t aB0 = smb;
    const uint32_t bB0 = smb + STG * A_BYTES;

    const int tid  = threadIdx.x;
    const int lane = tid & 31, wid = tid >> 5;
    const int wm = wid & 3, wn = wid >> 2;        // 4(m) x 2(n) warps
    const int g2 = lane >> 2, t4 = lane & 3;

    // block swizzle: 8 m-blocks per group sweep all 32 n-blocks (L2 reuse)
    const int pid = blockIdx.x;
    const int first_m = (pid >> 8) << 3;
    const int inner = pid & 255;
    const int m0 = (first_m + (inner & 7)) * GM_BM;
    const int n0 = (inner >> 3) * GM_BN;

    // cp.async mappings (256 threads, 4 chunks A + 4 chunks B each)
    const int a_m = tid >> 1, a_c0 = (tid & 1) * 4;   // A: 128 rows x 8 chunks
    const int b_k = tid >> 2, b_c0 = (tid & 3) * 4;   // B: 64 rows x 16 chunks

    const __half* srcA = g_Xh + (size_t)(m0 + a_m) * D_IN + a_c0 * 8;
    const __half* srcB = g_Wh + (size_t)b_k * N_FEAT + n0 + b_c0 * 8;

    uint32_t dstA[4], dstB[4];
#pragma unroll
    for (int c = 0; c < 4; c++) {
        const int cc = a_c0 + c;
        dstA[c] = aB0 + a_m * 128 + ((cc ^ (a_m & 7)) << 4);
        const int cn = b_c0 + c;
        dstB[c] = bB0 + b_k * 256 + ((cn ^ (b_k & 7)) << 4);
    }

    float acc[2][8][4];
#pragma unroll
    for (int mt = 0; mt < 2; mt++)
#pragma unroll
        for (int nt = 0; nt < 8; nt++)
#pragma unroll
            for (int r = 0; r < 4; r++) acc[mt][nt][r] = 0.0f;

    auto issue_tile = [&](int s) {
#pragma unroll
        for (int c = 0; c < 4; c++) {
            CP_ASYNC16(dstA[c] + s * A_BYTES, srcA + c * 8);
            CP_ASYNC16(dstB[c] + s * B_BYTES, srcB + c * 8);
        }
        srcA += GM_BK;
        srcB += (size_t)GM_BK * N_FEAT;
    };

#pragma unroll
    for (int s = 0; s < STG - 1; s++) { issue_tile(s); CP_COMMIT(); }

    int stage = 0;
    for (int it = 0; it < NIT; ++it) {
        CP_WAIT1();
        __syncthreads();
        if (it + STG - 1 < NIT) {
            int is = stage + (STG - 1);
            if (is >= STG) is -= STG;
            issue_tile(is);
        }
        CP_COMMIT();

        const uint32_t aB = aB0 + stage * A_BYTES;
        const uint32_t bB = bB0 + stage * B_BYTES;
#pragma unroll
        for (int ks = 0; ks < 4; ks++) {
            uint32_t af[2][4];
#pragma unroll
            for (int mt = 0; mt < 2; mt++) {
                const int row = wm * 32 + mt * 16 + (lane & 15);
                const int C = ks * 2 + (lane >> 4);
                const uint32_t addr = aB + row * 128 + ((C ^ (row & 7)) << 4);
                LDMATRIX_X4(af[mt][0], af[mt][1], af[mt][2], af[mt][3], addr);
            }
            uint32_t bf[8][2];
#pragma unroll
            for (int q = 0; q < 4; q++) {
                const int j = lane >> 3;
                const int krow = ks * 16 + (j & 1) * 8 + (lane & 7);
                const int chunk = wn * 8 + q * 2 + (j >> 1);
                const uint32_t addr = bB + krow * 256 + ((chunk ^ (krow & 7)) << 4);
                uint32_t r0, r1, r2, r3;
                LDMATRIX_X4_T(r0, r1, r2, r3, addr);
                bf[q * 2][0] = r0; bf[q * 2][1] = r1;
                bf[q * 2 + 1][0] = r2; bf[q * 2 + 1][1] = r3;
            }
#pragma unroll
            for (int mt = 0; mt < 2; mt++)
#pragma unroll
                for (int nt = 0; nt < 8; nt++)
                    mma_f16(acc[mt][nt], af[mt], bf[nt]);
        }
        if (++stage == STG) stage = 0;
    }

    // epilogue: bias + relu, direct STG.64
#pragma unroll
    for (int mt = 0; mt < 2; mt++) {
        const int r0 = m0 + wm * 32 + mt * 16 + g2;
#pragma unroll
        for (int nt = 0; nt < 8; nt++) {
            const int col = n0 + wn * 64 + nt * 8 + t4 * 2;
            const float2 bv = *reinterpret_cast<const float2*>(be + col);
            float2 o;
            o.x = fmaxf(acc[mt][nt][0] + bv.x, 0.0f);
            o.y = fmaxf(acc[mt][nt][1] + bv.y, 0.0f);
            *reinterpret_cast<float2*>(out + (size_t)r0 * N_FEAT + col) = o;
            o.x = fmaxf(acc[mt][nt][2] + bv.x, 0.0f);
            o.y = fmaxf(acc[mt][nt][3] + bv.y, 0.0f);
            *reinterpret_cast<float2*>(out + (size_t)(r0 + 8) * N_FEAT + col) = o;
        }
    }
}

// ---------------- Kernel 2: smem-row select + exact fixup + mask ------------
// Measured-best structure (R9/R12, ~580us): smem srow, 3-pass 256-bin radix,
// zero-skip, ballot-aggregated counts, regs 32 / occ ~96%. Exact fixup
// bit-identical to the blocked fp32 GEMM (256 slabs x 16 sequential FMAs,
// slab-order fold).
__global__ __launch_bounds__(512) void select_mask(
    float* __restrict__ out, const float* __restrict__ x,
    const float* __restrict__ pb, const float* __restrict__ be)
{
    __shared__ float    srow[N_FEAT];       // 16 KB
    __shared__ float    xc[D_IN];           // 16 KB
    __shared__ float    sp[8][256];         // 8 KB
    __shared__ unsigned hist[256], hs[256]; // 2 KB
    __shared__ unsigned wsum[16];
    __shared__ int      s_cidx[64];
    __shared__ float    s_cval[64];
    __shared__ int      sA, sNc;
    __shared__ unsigned sSel, sAbove, s_vbits;

    const int tid = threadIdx.x;
    const int lane = tid & 31, wid = tid >> 5;
    const int row = blockIdx.x;
    float* rowp = out + (size_t)row * N_FEAT;

#pragma unroll
    for (int i = tid; i < N_FEAT / 4; i += 512)
        *reinterpret_cast<float4*>(&srow[i * 4]) = reinterpret_cast<const float4*>(rowp)[i];
#pragma unroll
    for (int i = tid; i < D_IN / 4; i += 512) {
        float4 xv = reinterpret_cast<const float4*>(x + (size_t)row * D_IN)[i];
        const float4 pv = reinterpret_cast<const float4*>(pb)[i];
        xv.x -= pv.x; xv.y -= pv.y; xv.z -= pv.z; xv.w -= pv.w;
        *reinterpret_cast<float4*>(&xc[i * 4]) = xv;
    }
    if (tid == 0) { sA = 0; sNc = 0; s_vbits = 0x7F800000u; }
    __syncthreads();

    // ---- 3-pass radix select (24-bit prefix; truncation << WCAND), zero-skip
    unsigned prefix = 0u, hi_mask = 0u;
    int krem = TOPK;
#pragma unroll
    for (int pass = 0; pass < 3; pass++) {
        const int shift = 24 - 8 * pass;
        if (tid < 256) hist[tid] = 0u;
        __syncthreads();
#pragma unroll
        for (int i = 0; i < N_FEAT / 512; i++) {
            const unsigned bits = __float_as_uint(srow[tid + i * 512]);
            if (bits != 0u && (bits & hi_mask) == prefix)
                atomicAdd(&hist[(bits >> shift) & 0xFFu], 1u);
        }
        __syncthreads();
        if (wid < 8) {
            const int bin = wid * 32 + lane;
            unsigned s = hist[bin];
#pragma unroll
            for (int off = 1; off < 32; off <<= 1) {
                const unsigned t = __shfl_down_sync(0xFFFFFFFFu, s, off);
                if (lane + off < 32) s += t;
            }
            hs[bin] = s;
            if (lane == 0) wsum[wid] = s;
        }
        __syncthreads();
        if (wid == 0 && lane < 8) {
            const unsigned vv = wsum[lane];
            unsigned s = vv;
#pragma unroll
            for (int off = 1; off < 8; off <<= 1) {
                const unsigned t = __shfl_down_sync(0x000000FFu, s, off);
                if (lane + off < 8) s += t;
            }
            wsum[lane] = s - vv;
        }
        __syncthreads();
        if (tid < 256) hs[tid] += wsum[tid >> 5];
        __syncthreads();
        if (tid < 256) {
            const unsigned above = (tid == 255) ? 0u : hs[tid + 1];
            if (hs[tid] >= (unsigned)krem && above < (unsigned)krem) {
                sSel = (unsigned)tid; sAbove = above;
            }
        }
        __syncthreads();
        prefix |= (sSel << shift);
        hi_mask |= (0xFFu << shift);
        krem -= (int)sAbove;
        __syncthreads();
    }
    const float thr = __uint_as_float(prefix);
    const float whi = thr + WCAND, wlo = thr - WCAND;

    // ---- gather boundary candidates + ballot-aggregated definite-in count
    for (int i = tid; i < N_FEAT; i += 512) {
        const float a = srow[i];
        const unsigned bal = __ballot_sync(0xFFFFFFFFu, a > whi);
        if (lane == 0 && bal) atomicAdd(&sA, __popc(bal));
        if (a <= whi && a >= wlo) {
            const int p = atomicAdd(&sNc, 1);
            if (p < 64) s_cidx[p] = i;
        }
    }
    __syncthreads();

    const int nc = (sNc < 64) ? sNc : 64;
    const int kk = TOPK - sA;

    // ---- exact recompute, one candidate per warp (warps 0..7)
    if (wid < 8) {
        for (int c = wid; c < nc; c += 8) {
            const float4* w4 = reinterpret_cast<const float4*>(
                g_WT + (size_t)s_cidx[c] * D_IN);
            const float4* x4 = reinterpret_cast<const float4*>(xc);
#pragma unroll
            for (int s8 = 0; s8 < 8; s8++) {
                const int slab = s8 * 32 + lane;
                float part = 0.0f;
#pragma unroll
                for (int j = 0; j < 4; j++) {
                    const float4 a = x4[slab * 4 + j];
                    const float4 b = w4[slab * 4 + j];
                    part = fmaf(a.x, b.x, part);
                    part = fmaf(a.y, b.y, part);
                    part = fmaf(a.z, b.z, part);
                    part = fmaf(a.w, b.w, part);
                }
                sp[wid][slab] = part;
            }
            __syncwarp();
            if (lane == 0) {
                float acc = 0.0f;
#pragma unroll 8
                for (int j = 0; j < 256; j++) acc += sp[wid][j];  // slab order
                s_cval[c] = fmaxf(acc + be[s_cidx[c]], 0.0f);
            }
            __syncwarp();
        }
    }
    __syncthreads();

    // ---- kk-th largest exact candidate value
    if (tid < nc && kk >= 1) {
        const float cv = s_cval[tid];
        int g = 0;
        for (int j = 0; j < nc; j++) g += (s_cval[j] > cv);
        if (g <= kk - 1) atomicMin(&s_vbits, __float_as_uint(cv));
    }
    __syncthreads();

    const bool fallback = (sNc > 64) || (kk > nc) || (kk < 1);
    const float vstar = fallback ? thr : __uint_as_float(s_vbits);

    // ---- final mask, single global write
    for (int i = tid; i < N_FEAT; i += 512) {
        const float a = srow[i];
        float o;
        if (a > whi) o = a;
        else if (a >= wlo) {
            float ex = a; bool found = false;
            for (int c = 0; c < nc; c++)
                if (s_cidx[c] == i) { ex = s_cval[c]; found = true; break; }
            if (found) o = (ex >= vstar) ? ex : 0.0f;
            else       o = (a >= thr) ? a : 0.0f;
        } else o = 0.0f;
        rowp[i] = o;
    }
}

// ---------------------------------------------------------------------------
extern "C" void kernel_launch(void* const* d_in, const int* in_sizes, int n_in,
                              void* d_out, int out_size)
{
    const float* x  = (const float*)d_in[0];
    const float* pb = (const float*)d_in[1];
    const float* W  = (const float*)d_in[2];
    const float* be = (const float*)d_in[3];
    float* out = (float*)d_out;

    cudaFuncSetAttribute(encoder_gemm_h,
                         cudaFuncAttributeMaxDynamicSharedMemorySize, SM_BYTES);

    convert_x<<<(BATCH * D_IN / 4) / 256, 256>>>(x, pb);
    prep_w<<<dim3(N_FEAT / 32, D_IN / 32), dim3(32, 8)>>>(W);
    encoder_gemm_h<<<(BATCH / GM_BM) * (N_FEAT / GM_BN), 256, SM_BYTES>>>(be, out);
    select_mask<<<BATCH, 512>>>(out, x, pb, be);
}

// round 15
// speedup vs baseline: 1.2252x; 1.2252x over previous
#include <cuda_runtime.h>
#include <cuda_fp16.h>
#include <cstdint>

#define D_IN   4096
#define N_FEAT 4096
#define BATCH  16384
#define TOPK   128
#define WCAND  6.0e-3f   // was 1.2e-2; measured noise sigma=3.7e-4 -> ~8-sigma margin

// ---------------- device scratch (no allocs allowed) ------------------------
__device__ float  g_WT[(size_t)N_FEAT * D_IN];    // W^T fp32 [n][k] (exact fixup)
__device__ __half g_Wh[(size_t)D_IN * N_FEAT];    // W fp16  [k][n] (GEMM B)
__device__ __half g_Xh[(size_t)BATCH * D_IN];     // (x-pb) fp16 [m][k] (GEMM A)

// ---------------- helpers ---------------------------------------------------
__device__ __forceinline__ uint32_t smem_u32(const void* p) {
    uint32_t a;
    asm("{ .reg .u64 t; cvta.to.shared.u64 t, %1; cvt.u32.u64 %0, t; }"
        : "=r"(a) : "l"(p));
    return a;
}
__device__ __forceinline__ void mma_f16(float c[4], const uint32_t a[4],
                                        const uint32_t b[2]) {
    asm volatile(
        "mma.sync.aligned.m16n8k16.row.col.f32.f16.f16.f32 "
        "{%0,%1,%2,%3}, {%4,%5,%6,%7}, {%8,%9}, {%0,%1,%2,%3};"
        : "+f"(c[0]), "+f"(c[1]), "+f"(c[2]), "+f"(c[3])
        : "r"(a[0]), "r"(a[1]), "r"(a[2]), "r"(a[3]), "r"(b[0]), "r"(b[1]));
}
#define LDMATRIX_X4(r0, r1, r2, r3, addr) \
    asm volatile("ldmatrix.sync.aligned.m8n8.x4.shared.b16 {%0,%1,%2,%3}, [%4];" \
                 : "=r"(r0), "=r"(r1), "=r"(r2), "=r"(r3) : "r"(addr))
#define LDMATRIX_X4_T(r0, r1, r2, r3, addr) \
    asm volatile("ldmatrix.sync.aligned.m8n8.x4.trans.shared.b16 {%0,%1,%2,%3}, [%4];" \
                 : "=r"(r0), "=r"(r1), "=r"(r2), "=r"(r3) : "r"(addr))
#define CP_ASYNC16(dst_u32, src) \
    asm volatile("cp.async.cg.shared.global [%0], [%1], 16;" \
                 :: "r"(dst_u32), "l"(src) : "memory")
#define CP_COMMIT()  asm volatile("cp.async.commit_group;" ::: "memory")
#define CP_WAIT2()   asm volatile("cp.async.wait_group 2;" ::: "memory")

__device__ __forceinline__ uint32_t h2u(__half2 h) {
    return *reinterpret_cast<uint32_t*>(&h);
}

// ---------------- Prologue 0: x - pb -> fp16 g_Xh ---------------------------
__global__ __launch_bounds__(256) void convert_x(
    const float* __restrict__ x, const float* __restrict__ pb)
{
    const int i4 = blockIdx.x * 256 + threadIdx.x;
    const float4 v = reinterpret_cast<const float4*>(x)[i4];
    const float4 p = reinterpret_cast<const float4*>(pb)[i4 & (D_IN / 4 - 1)];
    uint2 o;
    o.x = h2u(__floats2half2_rn(v.x - p.x, v.y - p.y));
    o.y = h2u(__floats2half2_rn(v.z - p.z, v.w - p.w));
    reinterpret_cast<uint2*>(g_Xh)[i4] = o;
}

// ---------------- Prologue 1: W -> g_WT (fp32, transposed) + g_Wh (fp16) ----
__global__ void prep_w(const float* __restrict__ W) {
    __shared__ float t[32][33];
    const int n0 = blockIdx.x * 32, k0 = blockIdx.y * 32;
#pragma unroll
    for (int j = 0; j < 32; j += 8) {
        const int k = k0 + threadIdx.y + j;
        const float v = W[(size_t)k * N_FEAT + n0 + threadIdx.x];
        t[threadIdx.y + j][threadIdx.x] = v;
        g_Wh[(size_t)k * N_FEAT + n0 + threadIdx.x] = __float2half_rn(v);
    }
    __syncthreads();
#pragma unroll
    for (int j = 0; j < 32; j += 8)
        g_WT[(size_t)(n0 + threadIdx.y + j) * D_IN + k0 + threadIdx.x] =
            t[threadIdx.x][threadIdx.y + j];
}

// ---------------- Kernel 1: fp16 mma.sync GEMM + bias + relu ----------------
// PROVEN-BEST config (R8/R9, GEMM ~1.23ms): Block 128x128x32, 8 warps (4m x
// 2n), warp tile 32x64, 4-stage cp.async pipeline, 64KB smem -> 2 CTAs/SM.
#define GM_BM 128
#define GM_BN 128
#define GM_BK 32
#define NIT   (D_IN / GM_BK)              // 128
#define STG   4
#define A_BYTES (GM_BM * GM_BK * 2)       // 8192
#define B_BYTES (GM_BK * GM_BN * 2)       // 8192
#define SM_BYTES (STG * (A_BYTES + B_BYTES))  // 65536

__global__ __launch_bounds__(256, 2) void encoder_gemm_h(
    const float* __restrict__ be, float* __restrict__ out)
{
    extern __shared__ char sm[];
    const uint32_t smb = smem_u32(sm);
    const uint32_t aB0 = smb;
    const uint32_t bB0 = smb + STG * A_BYTES;

    const int tid  = threadIdx.x;
    const int lane = tid & 31, wid = tid >> 5;
    const int wm = wid & 3, wn = wid >> 2;
    const int g2 = lane >> 2, t4 = lane & 3;

    const int pid = blockIdx.x;
    const int first_m = (pid >> 8) << 3;
    const int inner = pid & 255;
    const int m0 = (first_m + (inner & 7)) * GM_BM;
    const int n0 = (inner >> 3) * GM_BN;

    const int a_m = tid >> 1, a_c0 = (tid & 1) * 2;
    const int b_k = tid >> 3, b_c0 = tid & 7;

    const __half* srcA = g_Xh + (size_t)(m0 + a_m) * D_IN + a_c0 * 8;
    const __half* srcB = g_Wh + (size_t)b_k * N_FEAT + n0 + b_c0 * 8;

    uint32_t dstA[2], dstB[2];
#pragma unroll
    for (int c = 0; c < 2; c++) {
        const int cc = a_c0 + c;
        dstA[c] = aB0 + a_m * 64 + ((cc ^ ((a_m >> 1) & 3)) << 4);
    }
#pragma unroll
    for (int p = 0; p < 2; p++) {
        const int cn = b_c0 + 8 * p;
        dstB[p] = bB0 + b_k * 256 + ((cn ^ (b_k & 7)) << 4);
    }

    float acc[2][8][4];
#pragma unroll
    for (int mt = 0; mt < 2; mt++)
#pragma unroll
        for (int nt = 0; nt < 8; nt++)
#pragma unroll
            for (int r = 0; r < 4; r++) acc[mt][nt][r] = 0.0f;

    auto issue_tile = [&](int s) {
        CP_ASYNC16(dstA[0] + s * A_BYTES, srcA);
        CP_ASYNC16(dstA[1] + s * A_BYTES, srcA + 8);
        CP_ASYNC16(dstB[0] + s * B_BYTES, srcB);
        CP_ASYNC16(dstB[1] + s * B_BYTES, srcB + 64);
        srcA += GM_BK;
        srcB += (size_t)GM_BK * N_FEAT;
    };

#pragma unroll
    for (int s = 0; s < STG - 1; s++) { issue_tile(s); CP_COMMIT(); }

    for (int it = 0; it < NIT; ++it) {
        CP_WAIT2();
        __syncthreads();
        if (it + STG - 1 < NIT) issue_tile((it + STG - 1) & (STG - 1));
        CP_COMMIT();

        const uint32_t aB = aB0 + (it & (STG - 1)) * A_BYTES;
        const uint32_t bB = bB0 + (it & (STG - 1)) * B_BYTES;
#pragma unroll
        for (int ks = 0; ks < 2; ks++) {
            uint32_t af[2][4];
#pragma unroll
            for (int mt = 0; mt < 2; mt++) {
                const int row = wm * 32 + mt * 16 + (lane & 15);
                const int C = ks * 2 + (lane >> 4);
                const uint32_t addr = aB + row * 64 + ((C ^ ((row >> 1) & 3)) << 4);
                LDMATRIX_X4(af[mt][0], af[mt][1], af[mt][2], af[mt][3], addr);
            }
            uint32_t bf[8][2];
#pragma unroll
            for (int q = 0; q < 4; q++) {
                const int j = lane >> 3;
                const int krow = ks * 16 + (j & 1) * 8 + (lane & 7);
                const int chunk = wn * 8 + q * 2 + (j >> 1);
                const uint32_t addr = bB + krow * 256 + ((chunk ^ (krow & 7)) << 4);
                uint32_t r0, r1, r2, r3;
                LDMATRIX_X4_T(r0, r1, r2, r3, addr);
                bf[q * 2][0] = r0; bf[q * 2][1] = r1;
                bf[q * 2 + 1][0] = r2; bf[q * 2 + 1][1] = r3;
            }
#pragma unroll
            for (int mt = 0; mt < 2; mt++)
#pragma unroll
                for (int nt = 0; nt < 8; nt++)
                    mma_f16(acc[mt][nt], af[mt], bf[nt]);
        }
    }

#pragma unroll
    for (int mt = 0; mt < 2; mt++) {
        const int r0 = m0 + wm * 32 + mt * 16 + g2;
#pragma unroll
        for (int nt = 0; nt < 8; nt++) {
            const int col = n0 + wn * 64 + nt * 8 + t4 * 2;
            const float2 bv = *reinterpret_cast<const float2*>(be + col);
            float2 o;
            o.x = fmaxf(acc[mt][nt][0] + bv.x, 0.0f);
            o.y = fmaxf(acc[mt][nt][1] + bv.y, 0.0f);
            *reinterpret_cast<float2*>(out + (size_t)r0 * N_FEAT + col) = o;
            o.x = fmaxf(acc[mt][nt][2] + bv.x, 0.0f);
            o.y = fmaxf(acc[mt][nt][3] + bv.y, 0.0f);
            *reinterpret_cast<float2*>(out + (size_t)(r0 + 8) * N_FEAT + col) = o;
        }
    }
}

// ---------------- Kernel 2: smem-row select + exact fixup + mask ------------
// Measured-floor structure (R9/R12 ~580us). Narrower WCAND (6e-3) halves the
// candidate count -> halves the dominant g_WT candidate DRAM traffic. Exact
// fixup bit-identical to the blocked fp32 GEMM (256 slabs x 16 sequential
// FMAs, slab-order fold).
__global__ __launch_bounds__(512) void select_mask(
    float* __restrict__ out, const float* __restrict__ x,
    const float* __restrict__ pb, const float* __restrict__ be)
{
    __shared__ float    srow[N_FEAT];       // 16 KB
    __shared__ float    xc[D_IN];           // 16 KB
    __shared__ float    sp[8][256];         // 8 KB
    __shared__ unsigned hist[256], hs[256]; // 2 KB
    __shared__ unsigned wsum[16];
    __shared__ int      s_cidx[64];
    __shared__ float    s_cval[64];
    __shared__ int      sA, sNc;
    __shared__ unsigned sSel, sAbove, s_vbits;

    const int tid = threadIdx.x;
    const int lane = tid & 31, wid = tid >> 5;
    const int row = blockIdx.x;
    float* rowp = out + (size_t)row * N_FEAT;

#pragma unroll
    for (int i = tid; i < N_FEAT / 4; i += 512)
        *reinterpret_cast<float4*>(&srow[i * 4]) = reinterpret_cast<const float4*>(rowp)[i];
#pragma unroll
    for (int i = tid; i < D_IN / 4; i += 512) {
        float4 xv = reinterpret_cast<const float4*>(x + (size_t)row * D_IN)[i];
        const float4 pv = reinterpret_cast<const float4*>(pb)[i];
        xv.x -= pv.x; xv.y -= pv.y; xv.z -= pv.z; xv.w -= pv.w;
        *reinterpret_cast<float4*>(&xc[i * 4]) = xv;
    }
    if (tid == 0) { sA = 0; sNc = 0; s_vbits = 0x7F800000u; }
    __syncthreads();

    // ---- 3-pass radix select (24-bit prefix; truncation << WCAND), zero-skip
    unsigned prefix = 0u, hi_mask = 0u;
    int krem = TOPK;
#pragma unroll
    for (int pass = 0; pass < 3; pass++) {
        const int shift = 24 - 8 * pass;
        if (tid < 256) hist[tid] = 0u;
        __syncthreads();
#pragma unroll
        for (int i = 0; i < N_FEAT / 512; i++) {
            const unsigned bits = __float_as_uint(srow[tid + i * 512]);
            if (bits != 0u && (bits & hi_mask) == prefix)
                atomicAdd(&hist[(bits >> shift) & 0xFFu], 1u);
        }
        __syncthreads();
        if (wid < 8) {
            const int bin = wid * 32 + lane;
            unsigned s = hist[bin];
#pragma unroll
            for (int off = 1; off < 32; off <<= 1) {
                const unsigned t = __shfl_down_sync(0xFFFFFFFFu, s, off);
                if (lane + off < 32) s += t;
            }
            hs[bin] = s;
            if (lane == 0) wsum[wid] = s;
        }
        __syncthreads();
        if (wid == 0 && lane < 8) {
            const unsigned vv = wsum[lane];
            unsigned s = vv;
#pragma unroll
            for (int off = 1; off < 8; off <<= 1) {
                const unsigned t = __shfl_down_sync(0x000000FFu, s, off);
                if (lane + off < 8) s += t;
            }
            wsum[lane] = s - vv;
        }
        __syncthreads();
        if (tid < 256) hs[tid] += wsum[tid >> 5];
        __syncthreads();
        if (tid < 256) {
            const unsigned above = (tid == 255) ? 0u : hs[tid + 1];
            if (hs[tid] >= (unsigned)krem && above < (unsigned)krem) {
                sSel = (unsigned)tid; sAbove = above;
            }
        }
        __syncthreads();
        prefix |= (sSel << shift);
        hi_mask |= (0xFFu << shift);
        krem -= (int)sAbove;
        __syncthreads();
    }
    const float thr = __uint_as_float(prefix);
    const float whi = thr + WCAND, wlo = thr - WCAND;

    // ---- gather boundary candidates + ballot-aggregated definite-in count
    for (int i = tid; i < N_FEAT; i += 512) {
        const float a = srow[i];
        const unsigned bal = __ballot_sync(0xFFFFFFFFu, a > whi);
        if (lane == 0 && bal) atomicAdd(&sA, __popc(bal));
        if (a <= whi && a >= wlo) {
            const int p = atomicAdd(&sNc, 1);
            if (p < 64) s_cidx[p] = i;
        }
    }
    __syncthreads();

    const int nc = (sNc < 64) ? sNc : 64;
    const int kk = TOPK - sA;

    // ---- exact recompute, one candidate per warp (warps 0..7)
    if (wid < 8) {
        for (int c = wid; c < nc; c += 8) {
            const float4* w4 = reinterpret_cast<const float4*>(
                g_WT + (size_t)s_cidx[c] * D_IN);
            const float4* x4 = reinterpret_cast<const float4*>(xc);
#pragma unroll
            for (int s8 = 0; s8 < 8; s8++) {
                const int slab = s8 * 32 + lane;
                float part = 0.0f;
#pragma unroll
                for (int j = 0; j < 4; j++) {
                    const float4 a = x4[slab * 4 + j];
                    const float4 b = w4[slab * 4 + j];
                    part = fmaf(a.x, b.x, part);
                    part = fmaf(a.y, b.y, part);
                    part = fmaf(a.z, b.z, part);
                    part = fmaf(a.w, b.w, part);
                }
                sp[wid][slab] = part;
            }
            __syncwarp();
            if (lane == 0) {
                float acc = 0.0f;
#pragma unroll 8
                for (int j = 0; j < 256; j++) acc += sp[wid][j];  // slab order
                s_cval[c] = fmaxf(acc + be[s_cidx[c]], 0.0f);
            }
            __syncwarp();
        }
    }
    __syncthreads();

    // ---- kk-th largest exact candidate value
    if (tid < nc && kk >= 1) {
        const float cv = s_cval[tid];
        int g = 0;
        for (int j = 0; j < nc; j++) g += (s_cval[j] > cv);
        if (g <= kk - 1) atomicMin(&s_vbits, __float_as_uint(cv));
    }
    __syncthreads();

    const bool fallback = (sNc > 64) || (kk > nc) || (kk < 1);
    const float vstar = fallback ? thr : __uint_as_float(s_vbits);

    // ---- final mask, single global write
    for (int i = tid; i < N_FEAT; i += 512) {
        const float a = srow[i];
        float o;
        if (a > whi) o = a;
        else if (a >= wlo) {
            float ex = a; bool found = false;
            for (int c = 0; c < nc; c++)
                if (s_cidx[c] == i) { ex = s_cval[c]; found = true; break; }
            if (found) o = (ex >= vstar) ? ex : 0.0f;
            else       o = (a >= thr) ? a : 0.0f;
        } else o = 0.0f;
        rowp[i] = o;
    }
}

// ---------------------------------------------------------------------------
extern "C" void kernel_launch(void* const* d_in, const int* in_sizes, int n_in,
                              void* d_out, int out_size)
{
    const float* x  = (const float*)d_in[0];
    const float* pb = (const float*)d_in[1];
    const float* W  = (const float*)d_in[2];
    const float* be = (const float*)d_in[3];
    float* out = (float*)d_out;

    cudaFuncSetAttribute(encoder_gemm_h,
                         cudaFuncAttributeMaxDynamicSharedMemorySize, SM_BYTES);

    convert_x<<<(BATCH * D_IN / 4) / 256, 256>>>(x, pb);
    prep_w<<<dim3(N_FEAT / 32, D_IN / 32), dim3(32, 8)>>>(W);
    encoder_gemm_h<<<(BATCH / GM_BM) * (N_FEAT / GM_BN), 256, SM_BYTES>>>(be, out);
    select_mask<<<BATCH, 512>>>(out, x, pb, be);
}